// round 16
// baseline (speedup 1.0000x reference)
#include <cuda_runtime.h>
#include <cuda_bf16.h>

#define MM   64
#define HH   128
#define INF_ 3
#define AA   64
#define NT   256

#define SH_STR 136   // bf16 units; 272B row stride (== 16 mod 128)
#define AT_STR 72    // bf16 units; 144B row stride (== 16 mod 128)

typedef __nv_bfloat16 bf16;
typedef unsigned int uint;

__device__ float g_c2l[HH], g_c2r[HH], g_c1l[INF_], g_c1r[INF_];
// W2 hi/lo interleaved, m16n8k16 B-fragment order:
// q = g_W2B[(ks*16+nu)*32 + lane] = {b0hi, b1hi, b0lo, b1lo}
__device__ uint4 g_W2B[8 * 16 * 32];

__device__ __forceinline__ uint pack2(float x, float y) {
    uint r;
    asm("cvt.rn.bf16x2.f32 %0, %1, %2;" : "=r"(r) : "f"(y), "f"(x));
    return r;
}
__device__ __forceinline__ float bflo(uint p) { return __uint_as_float(p << 16); }
__device__ __forceinline__ float bfhi(uint p) { return __uint_as_float(p & 0xffff0000u); }
__device__ __forceinline__ void split2(float x, float y, uint& h, uint& l) {
    h = pack2(x, y);
    l = pack2(x - bflo(h), y - bfhi(h));
}

__device__ __forceinline__ void mma16816(float4& d, uint a0, uint a1, uint a2, uint a3,
                                         uint b0, uint b1) {
    asm volatile(
        "mma.sync.aligned.m16n8k16.row.col.f32.bf16.bf16.f32 "
        "{%0,%1,%2,%3}, {%4,%5,%6,%7}, {%8,%9}, {%0,%1,%2,%3};"
        : "+f"(d.x), "+f"(d.y), "+f"(d.z), "+f"(d.w)
        : "r"(a0), "r"(a1), "r"(a2), "r"(a3), "r"(b0), "r"(b1));
}

__device__ __forceinline__ uint4 ldsm4(uint addr) {
    uint4 r;
    asm volatile("ldmatrix.sync.aligned.m8n8.x4.shared.b16 {%0,%1,%2,%3}, [%4];"
                 : "=r"(r.x), "=r"(r.y), "=r"(r.z), "=r"(r.w) : "r"(addr));
    return r;
}
__device__ __forceinline__ uint4 ldsm4t(uint addr) {
    uint4 r;
    asm volatile("ldmatrix.sync.aligned.m8n8.x4.trans.shared.b16 {%0,%1,%2,%3}, [%4];"
                 : "=r"(r.x), "=r"(r.y), "=r"(r.z), "=r"(r.w) : "r"(addr));
    return r;
}
__device__ __forceinline__ uint smaddr(const void* p) {
    return (uint)__cvta_generic_to_shared(p);
}

__global__ void precomp_kernel(const float* __restrict__ W1, const float* __restrict__ a1,
                               const float* __restrict__ W2, const float* __restrict__ a2) {
    int t = threadIdx.x;  // 128 threads
    float s1 = 0.f, s2 = 0.f;
#pragma unroll 8
    for (int j = 0; j < HH; j++) {
        float w = W2[t * HH + j];
        s1 = fmaf(w, a2[j], s1);
        s2 = fmaf(w, a2[HH + j], s2);
    }
    g_c2l[t] = s1;
    g_c2r[t] = s2;
    if (t < INF_) {
        float p = 0.f, q = 0.f;
#pragma unroll 8
        for (int j = 0; j < HH; j++) {
            float w = W1[t * HH + j];
            p = fmaf(w, a1[j], p);
            q = fmaf(w, a1[HH + j], q);
        }
        g_c1l[t] = p;
        g_c1r[t] = q;
    }
    for (int e = t; e < 8 * 16 * 32; e += 128) {
        int lane = e & 31;
        int nu = (e >> 5) & 15;
        int ks = e >> 9;
        int g = lane >> 2, tt = lane & 3;
        uint4 q;
        uint* qp = &q.x;
#pragma unroll
        for (int w = 0; w < 2; w++) {
            int k = ks * 16 + 2 * tt + 8 * w;
            int n = nu * 8 + g;
            float v0 = W2[k * HH + n];
            float v1 = W2[(k + 1) * HH + n];
            uint h, l;
            split2(v0, v1, h, l);
            qp[w] = h;
            qp[w + 2] = l;
        }
        g_W2B[e] = q;
    }
}

__device__ __forceinline__ float elu1(float x) {
    return (x > 0.f) ? x : (__expf(x) - 1.0f);
}

// 256-thread softmax core: row = tid>>2, 4 lanes x 16 cols. Normalized ev[16] in regs.
__device__ __forceinline__ void softmax_core(float* ev, const float* sSi,
                                             const float* sSj, int row, int l4) {
    float si = sSi[row];
    float sjv[16];
#pragma unroll
    for (int p = 0; p < 4; p++)
        *(float4*)&sjv[4 * p] = *(const float4*)(sSj + l4 * 16 + 4 * p);
    float m = -1e30f;
#pragma unroll
    for (int j = 0; j < 16; j++) {
        float x = si + sjv[j];
        x = (x > 0.f) ? x : 0.2f * x;
        ev[j] = x;
        m = fmaxf(m, x);
    }
    m = fmaxf(m, __shfl_xor_sync(0xffffffffu, m, 1));
    m = fmaxf(m, __shfl_xor_sync(0xffffffffu, m, 2));
    float s = 0.f;
#pragma unroll
    for (int j = 0; j < 16; j++) {
        float e = __expf(ev[j] - m);
        ev[j] = e;
        s += e;
    }
    s += __shfl_xor_sync(0xffffffffu, s, 1);
    s += __shfl_xor_sync(0xffffffffu, s, 2);
    float inv = 1.0f / s;
#pragma unroll
    for (int j = 0; j < 16; j++) ev[j] *= inv;
}

__global__ __launch_bounds__(NT, 4) void gat_kernel(
    const float* __restrict__ users, const float* __restrict__ W1,
    const float* __restrict__ W2,
    const float* __restrict__ mw1, const float* __restrict__ mb1,
    const float* __restrict__ mw2, const float* __restrict__ mb2,
    float* __restrict__ out, int B) {
    extern __shared__ char smb[];
    // region0 (34816 B): sH (before P5 stores) and Wh2 (after, same geometry) alias.
    bf16* sHhi  = (bf16*)(smb);                  // 64 x 136
    bf16* sHlo  = (bf16*)(smb + 17408);
    // region1 (18432 B): atHi+atLo bf16 (layer2 attn only; layer1 stays in registers)
    char* atHi  = smb + 34816;                   // 64 x 72 bf16 (144B rows)
    char* atLo  = smb + 44032;
    float* sF   = (float*)(smb + 53248);
    float* sU    = sF;              // 192 (dead after fused P2/P3a)
    float* sSi   = sF + 192;        // 64
    float* sSj   = sF + 256;        // 64
    float* sC2l  = sF + 320;        // 128
    float* sC2r  = sF + 448;        // 128
    float* scrA  = sF + 576;        // 256: union { sT(64x4) | sPoolQ(2x128) }
    float* sT    = scrA;
    float* sPoolQ= scrA;
    float* sR    = sF + 832;        // 32
    float* sO    = sF + 864;        // 128
    float* sSum  = sF + 992;        // 2

    const int tid  = threadIdx.x;
    const int b    = blockIdx.x;
    const int warp = tid >> 5;           // 0..7
    const int lane = tid & 31;
    const int mi2  = warp & 1;           // m32 strip
    const int nb2  = warp >> 1;          // n32 block (0..3)
    const int g    = lane >> 2;
    const int t4   = lane & 3;
    const int l7   = lane & 7;
    const int lb8  = (lane >> 3) & 1;
    const int lb16 = lane >> 4;
    const int row4 = tid >> 2;           // 0..63
    const int l4   = tid & 3;

    // ---- P0
    if (tid < MM * INF_) sU[tid] = users[b * (MM * INF_) + tid];
    if (tid < 128) { sC2l[tid] = g_c2l[tid]; sC2r[tid] = g_c2r[tid]; }
    __syncthreads();

    // ---- P1: layer1 si/sj via c1 trick
    if (tid < MM) {
        float u0 = sU[tid * 3], u1 = sU[tid * 3 + 1], u2 = sU[tid * 3 + 2];
        sSi[tid] = u0 * g_c1l[0] + u1 * g_c1l[1] + u2 * g_c1l[2];
        sSj[tid] = u0 * g_c1r[0] + u1 * g_c1r[1] + u2 * g_c1r[2];
    }
    __syncthreads();

    // ---- P2+P3a FUSED: softmax layer1 (registers) -> T = attn1 @ U (rank-3)
    {
        float ev[16];
        softmax_core(ev, sSi, sSj, row4, l4);
        const float* u = sU + l4 * 48;
        float t0 = 0.f, t1 = 0.f, t2 = 0.f;
#pragma unroll
        for (int j = 0; j < 16; j++) {
            float a = ev[j];
            t0 = fmaf(a, u[3 * j], t0);
            t1 = fmaf(a, u[3 * j + 1], t1);
            t2 = fmaf(a, u[3 * j + 2], t2);
        }
        t0 += __shfl_xor_sync(0xffffffffu, t0, 1);
        t1 += __shfl_xor_sync(0xffffffffu, t1, 1);
        t2 += __shfl_xor_sync(0xffffffffu, t2, 1);
        t0 += __shfl_xor_sync(0xffffffffu, t0, 2);
        t1 += __shfl_xor_sync(0xffffffffu, t1, 2);
        t2 += __shfl_xor_sync(0xffffffffu, t2, 2);
        if (!l4) {
            sT[row4 * 4 + 0] = t0;
            sT[row4 * 4 + 1] = t1;
            sT[row4 * 4 + 2] = t2;
            sT[row4 * 4 + 3] = 0.f;
        }
    }
    __syncthreads();

    // ---- P3b: h = elu(T @ W1), 2 adjacent cols x 16 rows per thread, packed STS.32
    {
        const int d2 = (tid & 63) * 2;
        const int q16 = tid >> 6;    // 0..3 -> rows q16*16..+15
        float wa0 = W1[d2],          wb0 = W1[d2 + 1];
        float wa1 = W1[HH + d2],     wb1 = W1[HH + d2 + 1];
        float wa2 = W1[2 * HH + d2], wb2 = W1[2 * HH + d2 + 1];
        uint* rh = (uint*)sHhi;
        uint* rl = (uint*)sHlo;
#pragma unroll
        for (int r = 0; r < 16; r++) {
            int row = q16 * 16 + r;
            float4 tt = *(const float4*)&sT[row * 4];
            float xa = elu1(fmaf(tt.x, wa0, fmaf(tt.y, wa1, tt.z * wa2)));
            float xb = elu1(fmaf(tt.x, wb0, fmaf(tt.y, wb1, tt.z * wb2)));
            uint h, l;
            split2(xa, xb, h, l);
            rh[row * (SH_STR / 2) + (d2 >> 1)] = h;
            rl[row * (SH_STR / 2) + (d2 >> 1)] = l;
        }
    }
    __syncthreads();

    // ---- P4: layer2 si/sj = h @ c2 (64 rows x 4 lanes), vectorized LDS.128
    {
        uint hv[16], lv[16];
#pragma unroll
        for (int p = 0; p < 4; p++) {
            *(uint4*)&hv[4 * p] = *(const uint4*)(sHhi + row4 * SH_STR + l4 * 32 + 8 * p);
            *(uint4*)&lv[4 * p] = *(const uint4*)(sHlo + row4 * SH_STR + l4 * 32 + 8 * p);
        }
        const float* cl = sC2l + l4 * 32;
        const float* cr = sC2r + l4 * 32;
        float s1 = 0.f, s2 = 0.f;
#pragma unroll
        for (int p = 0; p < 16; p++) {
            uint h2 = hv[p], l2 = lv[p];
            float h0 = bflo(h2) + bflo(l2);
            float h1 = bfhi(h2) + bfhi(l2);
            s1 = fmaf(h0, cl[2 * p], s1);     s2 = fmaf(h0, cr[2 * p], s2);
            s1 = fmaf(h1, cl[2 * p + 1], s1); s2 = fmaf(h1, cr[2 * p + 1], s2);
        }
        s1 += __shfl_xor_sync(0xffffffffu, s1, 1);
        s2 += __shfl_xor_sync(0xffffffffu, s2, 1);
        s1 += __shfl_xor_sync(0xffffffffu, s1, 2);
        s2 += __shfl_xor_sync(0xffffffffu, s2, 2);
        if (!l4) { sSi[row4] = s1; sSj[row4] = s2; }
    }

    // ---- P5: Wh2 = h @ W2, 8 warps m32n32, LDSM A-frags
    {
        float4 acc5[2][4];
#pragma unroll
        for (int h = 0; h < 2; h++)
#pragma unroll
            for (int f = 0; f < 4; f++) acc5[h][f] = make_float4(0.f, 0.f, 0.f, 0.f);
        const int arowl = mi2 * 32 + l7 + lb8 * 8;
        uint aHi0 = smaddr(sHhi) + arowl * (SH_STR * 2) + lb16 * 16;
        uint aLo0 = smaddr(sHlo) + arowl * (SH_STR * 2) + lb16 * 16;
#pragma unroll
        for (int ks = 0; ks < 8; ks++) {
            uint koff = ks * 32;
            uint4 ah[2], al[2];
#pragma unroll
            for (int h = 0; h < 2; h++) {
                ah[h] = ldsm4(aHi0 + h * (16 * SH_STR * 2) + koff);
                al[h] = ldsm4(aLo0 + h * (16 * SH_STR * 2) + koff);
            }
#pragma unroll
            for (int f = 0; f < 4; f++) {
                int nu = nb2 * 4 + f;
                uint4 q = g_W2B[(ks * 16 + nu) * 32 + lane];
#pragma unroll
                for (int h = 0; h < 2; h++) {
                    mma16816(acc5[h][f], ah[h].x, ah[h].y, ah[h].z, ah[h].w, q.x, q.y);
                    mma16816(acc5[h][f], ah[h].x, ah[h].y, ah[h].z, ah[h].w, q.z, q.w);
                    mma16816(acc5[h][f], al[h].x, al[h].y, al[h].z, al[h].w, q.x, q.y);
                }
            }
        }
        __syncthreads();   // all reads of sH done -> safe to overwrite region0 with Wh2
        uint* wh = (uint*)sHhi;
        uint* wl = (uint*)sHlo;
#pragma unroll
        for (int h = 0; h < 2; h++) {
            int r0 = mi2 * 32 + h * 16 + g;
#pragma unroll
            for (int f = 0; f < 4; f++) {
                int cu = (nb2 * 32 + f * 8 + 2 * t4) >> 1;
                float4 v = acc5[h][f];
                uint hw, lw;
                split2(v.x, v.y, hw, lw);
                wh[r0 * (SH_STR / 2) + cu] = hw;
                wl[r0 * (SH_STR / 2) + cu] = lw;
                split2(v.z, v.w, hw, lw);
                wh[(r0 + 8) * (SH_STR / 2) + cu] = hw;
                wl[(r0 + 8) * (SH_STR / 2) + cu] = lw;
            }
        }
    }
    __syncthreads();

    // ---- P6: softmax layer 2 -> attn bf16 hi/lo
    {
        float ev[16];
        softmax_core(ev, sSi, sSj, row4, l4);
        uint4 vh, vl;
        uint* ph = &vh.x;
        uint* pl = &vl.x;
#pragma unroll
        for (int p = 0; p < 4; p++) split2(ev[2 * p], ev[2 * p + 1], ph[p], pl[p]);
        *(uint4*)(atHi + row4 * (AT_STR * 2) + l4 * 32) = vh;
        *(uint4*)(atLo + row4 * (AT_STR * 2) + l4 * 32) = vl;
#pragma unroll
        for (int p = 0; p < 4; p++) split2(ev[8 + 2 * p], ev[9 + 2 * p], ph[p], pl[p]);
        *(uint4*)(atHi + row4 * (AT_STR * 2) + l4 * 32 + 16) = vh;
        *(uint4*)(atLo + row4 * (AT_STR * 2) + l4 * 32 + 16) = vl;
    }
    __syncthreads();

    // ---- P7: h2 = elu(attn2 @ Wh2), 8 warps m32n32; A via LDSM, B via LDSM.trans
    {
        float4 acc[2][4];
#pragma unroll
        for (int h = 0; h < 2; h++)
#pragma unroll
            for (int f = 0; f < 4; f++) acc[h][f] = make_float4(0.f, 0.f, 0.f, 0.f);
        const int arowl = mi2 * 32 + l7 + lb8 * 8;
        uint aHi0 = smaddr(atHi) + arowl * (AT_STR * 2) + lb16 * 16;
        uint aLo0 = smaddr(atLo) + arowl * (AT_STR * 2) + lb16 * 16;
        const int krl = l7 + lb8 * 8;
        uint bHi0 = smaddr(sHhi) + krl * (SH_STR * 2);
        uint bLo0 = smaddr(sHlo) + krl * (SH_STR * 2);
#pragma unroll
        for (int ks = 0; ks < 4; ks++) {
            uint4 ah[2], al[2];
#pragma unroll
            for (int h = 0; h < 2; h++) {
                ah[h] = ldsm4(aHi0 + h * (16 * AT_STR * 2) + ks * 32);
                al[h] = ldsm4(aLo0 + h * (16 * AT_STR * 2) + ks * 32);
            }
#pragma unroll
            for (int fp = 0; fp < 2; fp++) {
                int nu = nb2 * 4 + fp * 2 + lb16;
                uint boff = ks * 16 * (SH_STR * 2) + nu * 16;
                uint4 bh = ldsm4t(bHi0 + boff);
                uint4 bl = ldsm4t(bLo0 + boff);
                int f0 = fp * 2, f1 = fp * 2 + 1;
#pragma unroll
                for (int h = 0; h < 2; h++) {
                    mma16816(acc[h][f0], ah[h].x, ah[h].y, ah[h].z, ah[h].w, bh.x, bh.y);
                    mma16816(acc[h][f0], ah[h].x, ah[h].y, ah[h].z, ah[h].w, bl.x, bl.y);
                    mma16816(acc[h][f0], al[h].x, al[h].y, al[h].z, al[h].w, bh.x, bh.y);
                    mma16816(acc[h][f1], ah[h].x, ah[h].y, ah[h].z, ah[h].w, bh.z, bh.w);
                    mma16816(acc[h][f1], ah[h].x, ah[h].y, ah[h].z, ah[h].w, bl.z, bl.w);
                    mma16816(acc[h][f1], al[h].x, al[h].y, al[h].z, al[h].w, bh.z, bh.w);
                }
            }
        }
#pragma unroll
        for (int f = 0; f < 4; f++) {
            float p0 = -1e30f, p1 = -1e30f;
#pragma unroll
            for (int h = 0; h < 2; h++) {
                p0 = fmaxf(p0, fmaxf(elu1(acc[h][f].x), elu1(acc[h][f].z)));
                p1 = fmaxf(p1, fmaxf(elu1(acc[h][f].y), elu1(acc[h][f].w)));
            }
#pragma unroll
            for (int off = 4; off < 32; off <<= 1) {
                p0 = fmaxf(p0, __shfl_xor_sync(0xffffffffu, p0, off));
                p1 = fmaxf(p1, __shfl_xor_sync(0xffffffffu, p1, off));
            }
            if (lane < 4) {
                int c = nb2 * 32 + f * 8 + 2 * lane;
                *(float2*)&sPoolQ[mi2 * 128 + c] = make_float2(p0, p1);
            }
        }
    }
    __syncthreads();

    // ---- P8 (P7b fused): hidden = relu(pooled @ mw1 + mb1); pool combined inline
    {
        int col = tid >> 3, l8 = tid & 7;
        float acc = 0.f;
        const float* pa = sPoolQ + l8 * 16;
        const float* pb = sPoolQ + 128 + l8 * 16;
#pragma unroll
        for (int k = 0; k < 16; k++) {
            float pv = fmaxf(pa[k], pb[k]);
            acc = fmaf(pv, mw1[(l8 * 16 + k) * 32 + col], acc);
        }
        acc += __shfl_xor_sync(0xffffffffu, acc, 1);
        acc += __shfl_xor_sync(0xffffffffu, acc, 2);
        acc += __shfl_xor_sync(0xffffffffu, acc, 4);
        if (!l8) sR[col] = fmaxf(acc + mb1[col], 0.f);
    }
    __syncthreads();

    // ---- P9
    if (tid < 128) {
        float acc = mb2[tid];
#pragma unroll
        for (int m = 0; m < 32; m++) acc = fmaf(sR[m], mw2[m * HH + tid], acc);
        sO[tid] = fmaxf(acc, 0.f) + 1e-6f;
    }
    __syncthreads();

    // ---- P10
    if (tid < 2) {
        float s = 0.f;
        const float* p = sO + tid * 64;
#pragma unroll 8
        for (int j = 0; j < 64; j++) s += p[j];
        sSum[tid] = s;
    }
    __syncthreads();

    // ---- P11: normalize & write. power[B,A] then delta[B,A]
    if (tid < 128) {
        const float Bmax = 2.0f * 50.0f - 63.0f * 0.025f;  // 98.425
        const float PMAX = 1.0f;
        if (tid < 64) {
            out[(size_t)B * AA + (size_t)b * AA + tid] = Bmax * sO[tid] / (sSum[0] + 1e-6f);
        } else {
            out[(size_t)b * AA + (tid - 64)] = PMAX * sO[tid] / (sSum[1] + 1e-6f);
        }
    }
}

static const int SMEM_BYTES = 53248 + 994 * 4;   // 57224

extern "C" void kernel_launch(void* const* d_in, const int* in_sizes, int n_in,
                              void* d_out, int out_size) {
    const float* users = (const float*)d_in[0];
    const float* W1    = (const float*)d_in[1];
    const float* a1    = (const float*)d_in[2];
    const float* W2    = (const float*)d_in[3];
    const float* a2    = (const float*)d_in[4];
    const float* mw1   = (const float*)d_in[5];
    const float* mb1   = (const float*)d_in[6];
    const float* mw2   = (const float*)d_in[7];
    const float* mb2   = (const float*)d_in[8];
    float* out = (float*)d_out;

    int B = in_sizes[0] / (MM * INF_);

    cudaFuncSetAttribute(gat_kernel, cudaFuncAttributeMaxDynamicSharedMemorySize, SMEM_BYTES);

    precomp_kernel<<<1, 128>>>(W1, a1, W2, a2);
    gat_kernel<<<B, NT, SMEM_BYTES>>>(users, W1, W2, mw1, mb1, mw2, mb2, out, B);
}